// round 15
// baseline (speedup 1.0000x reference)
#include <cuda_runtime.h>
#include <math.h>
#include <stdint.h>

// ---------------------------------------------------------------------------
// iTransformer encoder, round 15: R13 bf16 3-term GEMM + attention fully on
// bf16 tensor cores (QK^T from R14 + AV via split probs/values). fp32 softmax.
// B=16, S=1024, T=512, D=256, H=8, DH=32, L=4, FF=1024. M = B*S = 16384.
// ---------------------------------------------------------------------------

#define M_ROWS 16384
#define D_MODEL 256
#define T_IN 512
#define FF_DIM 1024
#define N_HEADS 8
#define DH 32
#define SEQ 1024
#define N_LAYERS 4

__device__ float g_y[M_ROWS * D_MODEL];
__device__ float g_h[M_ROWS * D_MODEL];
__device__ float g_qkv[M_ROWS * 3 * D_MODEL];
__device__ float g_att[M_ROWS * D_MODEL];
__device__ float g_ff[M_ROWS * FF_DIM];
__device__ float2 g_stats[M_ROWS];
__device__ float2 g_rope[SEQ * 16];

__device__ __forceinline__ void mma_bf16(float* d, const uint32_t* a,
                                         const uint32_t* b) {
  asm("mma.sync.aligned.m16n8k16.row.col.f32.bf16.bf16.f32 "
      "{%0,%1,%2,%3}, {%4,%5,%6,%7}, {%8,%9}, {%0,%1,%2,%3};\n"
      : "+f"(d[0]), "+f"(d[1]), "+f"(d[2]), "+f"(d[3])
      : "r"(a[0]), "r"(a[1]), "r"(a[2]), "r"(a[3]), "r"(b[0]), "r"(b[1]));
}

// Truncation split (ALL ALU). e0 = even k -> low half, e1 = odd k -> high half.
#define SPLIT_PAIR(e0, e1, hp, lp)                                             \
  {                                                                            \
    uint32_t u0 = __float_as_uint(e0), u1 = __float_as_uint(e1);               \
    float l0 = (e0) - __uint_as_float(u0 & 0xffff0000u);                       \
    float l1 = (e1) - __uint_as_float(u1 & 0xffff0000u);                       \
    hp = __byte_perm(u0, u1, 0x7632);                                          \
    lp = __byte_perm(__float_as_uint(l0), __float_as_uint(l1), 0x7632);        \
  }

// ---------------------------------------------------------------------------
// Per-row LN stats.
// ---------------------------------------------------------------------------
__global__ __launch_bounds__(256) void ln_stats_kernel(
    const float* __restrict__ in, float2* __restrict__ st) {
  const int warp = threadIdx.x >> 5;
  const int lane = threadIdx.x & 31;
  const int row = blockIdx.x * 8 + warp;
  const float* p = in + (size_t)row * D_MODEL + lane * 8;
  float4 v0 = *(const float4*)p;
  float4 v1 = *(const float4*)(p + 4);
  float v[8] = {v0.x, v0.y, v0.z, v0.w, v1.x, v1.y, v1.z, v1.w};
  float s = 0.f;
#pragma unroll
  for (int i = 0; i < 8; i++) s += v[i];
#pragma unroll
  for (int o = 16; o > 0; o >>= 1) s += __shfl_xor_sync(0xffffffffu, s, o);
  float mean = s * (1.0f / 256.0f);
  float s2 = 0.f;
#pragma unroll
  for (int i = 0; i < 8; i++) {
    float d = v[i] - mean;
    s2 += d * d;
  }
#pragma unroll
  for (int o = 16; o > 0; o >>= 1) s2 += __shfl_xor_sync(0xffffffffu, s2, o);
  float var = s2 * (1.0f / 256.0f);
  if (lane == 0) st[row] = make_float2(mean, rsqrtf(var + 1e-5f));
}

// ---------------------------------------------------------------------------
// RoPE table.
// ---------------------------------------------------------------------------
__global__ __launch_bounds__(256) void rope_table_kernel(
    float2* __restrict__ tab) {
  int idx = blockIdx.x * 256 + threadIdx.x;
  int j = idx & 15;
  int s = idx >> 4;
  float inv_freq = 1.0f / powf(10000.0f, (float)j * 0.0625f);
  float c, sn;
  sincosf((float)s * inv_freq, &c, &sn);
  tab[idx] = make_float2(c, sn);
}

// ---------------------------------------------------------------------------
// 3-term BF16x2 GEMM (R13, proven).
// ---------------------------------------------------------------------------
#define GEMM_SMEM_BYTES (2 * 2 * 128 * 4 * 8 * 2)

#define LN_APPLY()                                                             \
  do {                                                                         \
    if (LNA) {                                                                 \
      const float* gp = lng + k0 + lsl * 8;                                    \
      const float* bp = lnb + k0 + lsl * 8;                                    \
      float4 gg0 = *(const float4*)gp, gg1 = *(const float4*)(gp + 4);         \
      float4 bb0 = *(const float4*)bp, bb1 = *(const float4*)(bp + 4);         \
      va0.x = fmaf((va0.x - mu) * rsd, gg0.x, bb0.x);                          \
      va0.y = fmaf((va0.y - mu) * rsd, gg0.y, bb0.y);                          \
      va0.z = fmaf((va0.z - mu) * rsd, gg0.z, bb0.z);                          \
      va0.w = fmaf((va0.w - mu) * rsd, gg0.w, bb0.w);                          \
      va1.x = fmaf((va1.x - mu) * rsd, gg1.x, bb1.x);                          \
      va1.y = fmaf((va1.y - mu) * rsd, gg1.y, bb1.y);                          \
      va1.z = fmaf((va1.z - mu) * rsd, gg1.z, bb1.z);                          \
      va1.w = fmaf((va1.w - mu) * rsd, gg1.w, bb1.w);                          \
    }                                                                          \
  } while (0)

#define STAGE_STORE(BUF)                                                       \
  do {                                                                         \
    float av[8] = {va0.x, va0.y, va0.z, va0.w, va1.x, va1.y, va1.z, va1.w};    \
    float bv[8] = {vb0.x, vb0.y, vb0.z, vb0.w, vb1.x, vb1.y, vb1.z, vb1.w};    \
    _Pragma("unroll") for (int c = 0; c < 4; c++) {                            \
      uint32_t ah, al, bh, bl;                                                 \
      SPLIT_PAIR(av[2 * c], av[2 * c + 1], ah, al);                            \
      SPLIT_PAIR(bv[2 * c], bv[2 * c + 1], bh, bl);                            \
      As[BUF][lsl][lrow][c] =                                                  \
          make_float2(__uint_as_float(ah), __uint_as_float(al));               \
      Bs[BUF][lsl][lrow][c] =                                                  \
          make_float2(__uint_as_float(bh), __uint_as_float(bl));               \
    }                                                                          \
  } while (0)

#define COMPUTE_STAGE(BUF)                                                     \
  {                                                                            \
    uint32_t bfH[4][2], bfL[4][2];                                             \
    _Pragma("unroll") for (int nt = 0; nt < 4; nt++) {                         \
      const int rw = wn * 32 + nt * 8 + gid;                                   \
      float2 q0 = Bs[BUF][0][rw][tg];                                          \
      float2 q1 = Bs[BUF][1][rw][tg];                                          \
      bfH[nt][0] = __float_as_uint(q0.x); bfH[nt][1] = __float_as_uint(q1.x);  \
      bfL[nt][0] = __float_as_uint(q0.y); bfL[nt][1] = __float_as_uint(q1.y);  \
    }                                                                          \
    _Pragma("unroll") for (int mh = 0; mh < 2; mh++) {                         \
      uint32_t afH[2][4], afL[2][4];                                           \
      _Pragma("unroll") for (int mi = 0; mi < 2; mi++) {                       \
        const int rb = wm * 64 + (mh * 2 + mi) * 16 + gid;                     \
        float2 a00 = As[BUF][0][rb][tg];                                       \
        float2 a01 = As[BUF][0][rb + 8][tg];                                   \
        float2 a10 = As[BUF][1][rb][tg];                                       \
        float2 a11 = As[BUF][1][rb + 8][tg];                                   \
        afH[mi][0] = __float_as_uint(a00.x);                                   \
        afH[mi][1] = __float_as_uint(a01.x);                                   \
        afH[mi][2] = __float_as_uint(a10.x);                                   \
        afH[mi][3] = __float_as_uint(a11.x);                                   \
        afL[mi][0] = __float_as_uint(a00.y);                                   \
        afL[mi][1] = __float_as_uint(a01.y);                                   \
        afL[mi][2] = __float_as_uint(a10.y);                                   \
        afL[mi][3] = __float_as_uint(a11.y);                                   \
      }                                                                        \
      _Pragma("unroll") for (int mi = 0; mi < 2; mi++)                         \
          _Pragma("unroll") for (int nt = 0; nt < 4; nt++)                     \
          mma_bf16(acc[mh * 2 + mi][nt], afH[mi], bfH[nt]);                    \
      _Pragma("unroll") for (int mi = 0; mi < 2; mi++)                         \
          _Pragma("unroll") for (int nt = 0; nt < 4; nt++)                     \
          mma_bf16(acc[mh * 2 + mi][nt], afH[mi], bfL[nt]);                    \
      _Pragma("unroll") for (int mi = 0; mi < 2; mi++)                         \
          _Pragma("unroll") for (int nt = 0; nt < 4; nt++)                     \
          mma_bf16(acc[mh * 2 + mi][nt], afL[mi], bfH[nt]);                    \
    }                                                                          \
  }

template <bool LNA, bool RELU, bool RES, bool ROPE>
__global__ __launch_bounds__(256, 2) void gemm_kernel(
    const float* __restrict__ A, const float* __restrict__ B,
    const float* __restrict__ bias, const float* __restrict__ res,
    const float2* __restrict__ stats, const float* __restrict__ lng,
    const float* __restrict__ lnb, const float2* __restrict__ rope,
    float* __restrict__ C, int M, int N, int K) {
  extern __shared__ float2 smem_dyn[];
  typedef float2 (*SmemT)[2][128][4];
  SmemT As = (SmemT)smem_dyn;
  SmemT Bs = (SmemT)(smem_dyn + 2 * 2 * 128 * 4);

  const int tid = threadIdx.x;
  const int lane = tid & 31;
  const int warp = tid >> 5;
  const int wm = warp >> 2;
  const int wn = warp & 3;
  const int gid = lane >> 2;
  const int tg = lane & 3;

  const int m0 = blockIdx.y * 128;
  const int n0 = blockIdx.x * 128;

  const int lrow = tid >> 1;
  const int lsl = tid & 1;

  const float* Ap = A + (size_t)(m0 + lrow) * K + lsl * 8;
  const float* Bp = B + (size_t)(n0 + lrow) * K + lsl * 8;

  float mu = 0.f, rsd = 1.f;
  if (LNA) {
    float2 st = stats[m0 + lrow];
    mu = st.x;
    rsd = st.y;
  }

  float acc[4][4][4];
#pragma unroll
  for (int i = 0; i < 4; i++)
#pragma unroll
    for (int j = 0; j < 4; j++)
#pragma unroll
      for (int r = 0; r < 4; r++) acc[i][j][r] = 0.f;

  {
    const int k0 = 0;
    float4 va0 = *(const float4*)(Ap);
    float4 va1 = *(const float4*)(Ap + 4);
    float4 vb0 = *(const float4*)(Bp);
    float4 vb1 = *(const float4*)(Bp + 4);
    LN_APPLY();
    STAGE_STORE(0);
    (void)k0;
  }
  __syncthreads();

  int buf = 0;
  for (int k0 = 16; k0 < K; k0 += 16) {
    float4 va0 = *(const float4*)(Ap + k0);
    float4 va1 = *(const float4*)(Ap + k0 + 4);
    float4 vb0 = *(const float4*)(Bp + k0);
    float4 vb1 = *(const float4*)(Bp + k0 + 4);
    LN_APPLY();
    COMPUTE_STAGE(buf);
    const int nxt = buf ^ 1;
    STAGE_STORE(nxt);
    __syncthreads();
    buf = nxt;
  }
  COMPUTE_STAGE(buf);

  const bool doRot = ROPE && (n0 + wn * 32) < 2 * D_MODEL;

#pragma unroll
  for (int mt = 0; mt < 4; mt++) {
    const int row = m0 + wm * 64 + mt * 16 + gid;
    float4 rr[4];
#pragma unroll
    for (int nt = 0; nt < 4; nt++) {
      const int col = n0 + wn * 32 + nt * 8 + tg * 2;
      float2 bb = *(const float2*)&bias[col];
      rr[nt] = make_float4(acc[mt][nt][0] + bb.x, acc[mt][nt][1] + bb.y,
                           acc[mt][nt][2] + bb.x, acc[mt][nt][3] + bb.y);
    }
    if (doRot) {
      const int s = row & (SEQ - 1);
      const int s8 = s + 8;
#pragma unroll
      for (int p = 0; p < 2; p++) {
        const int j0 = p * 8 + tg * 2;
        float2 c0 = rope[s * 16 + j0];
        float2 c1 = rope[s * 16 + j0 + 1];
        float2 d0 = rope[s8 * 16 + j0];
        float2 d1 = rope[s8 * 16 + j0 + 1];
        float4 a = rr[p], q = rr[p + 2];
        rr[p].x = a.x * c0.x - q.x * c0.y;
        rr[p + 2].x = q.x * c0.x + a.x * c0.y;
        rr[p].y = a.y * c1.x - q.y * c1.y;
        rr[p + 2].y = q.y * c1.x + a.y * c1.y;
        rr[p].z = a.z * d0.x - q.z * d0.y;
        rr[p + 2].z = q.z * d0.x + a.z * d0.y;
        rr[p].w = a.w * d1.x - q.w * d1.y;
        rr[p + 2].w = q.w * d1.x + a.w * d1.y;
      }
    }
#pragma unroll
    for (int nt = 0; nt < 4; nt++) {
      const int col = n0 + wn * 32 + nt * 8 + tg * 2;
      float2 r0 = make_float2(rr[nt].x, rr[nt].y);
      float2 r1 = make_float2(rr[nt].z, rr[nt].w);
      if (RELU) {
        r0.x = fmaxf(r0.x, 0.f); r0.y = fmaxf(r0.y, 0.f);
        r1.x = fmaxf(r1.x, 0.f); r1.y = fmaxf(r1.y, 0.f);
      }
      if (RES) {
        float2 q0 = *(const float2*)&res[(size_t)row * N + col];
        float2 q1 = *(const float2*)&res[(size_t)(row + 8) * N + col];
        r0.x += q0.x; r0.y += q0.y;
        r1.x += q1.x; r1.y += q1.y;
      }
      *(float2*)&C[(size_t)row * N + col] = r0;
      *(float2*)&C[(size_t)(row + 8) * N + col] = r1;
    }
  }
}

// ---------------------------------------------------------------------------
// Full LayerNorm (tokenize + final).
// ---------------------------------------------------------------------------
__global__ __launch_bounds__(256) void ln_kernel(
    const float* __restrict__ in, const float* __restrict__ g,
    const float* __restrict__ b, float* __restrict__ out) {
  const int row = blockIdx.x;
  const int t = threadIdx.x;
  float v = in[(size_t)row * D_MODEL + t];

  float s = v;
#pragma unroll
  for (int o = 16; o > 0; o >>= 1) s += __shfl_xor_sync(0xffffffffu, s, o);
  __shared__ float ws[8];
  __shared__ float ws2[8];
  if ((t & 31) == 0) ws[t >> 5] = s;
  __syncthreads();
  float mean = (ws[0] + ws[1] + ws[2] + ws[3] + ws[4] + ws[5] + ws[6] + ws[7]) *
               (1.0f / 256.0f);
  float d = v - mean;
  float s2 = d * d;
#pragma unroll
  for (int o = 16; o > 0; o >>= 1) s2 += __shfl_xor_sync(0xffffffffu, s2, o);
  if ((t & 31) == 0) ws2[t >> 5] = s2;
  __syncthreads();
  float var = (ws2[0] + ws2[1] + ws2[2] + ws2[3] + ws2[4] + ws2[5] + ws2[6] +
               ws2[7]) * (1.0f / 256.0f);
  out[(size_t)row * D_MODEL + t] = d * rsqrtf(var + 1e-5f) * g[t] + b[t];
}

// ---------------------------------------------------------------------------
// Attention: QK^T and AV both on bf16 tensor cores (3-term), fp32 softmax.
// Grid (S/64, B*H), 256 threads (8 warps).
// QK warp map: rows (warp>>1)*16, cols (warp&1)*32 (R14, proven).
// AV warp map: rows (warp>>2)*32 (2 m-tiles), cols (warp&3)*8 (1 n-tile).
// Buffers (dynamic smem): QP/KP packed q/k pairs; VP packed V^T pairs;
// SP fp32 scores; PP packed prob pairs; cfs/lfin row factors.
// ---------------------------------------------------------------------------
#define BQ 64
#define BKT 64
#define ATTN_SMEM_BYTES 62208
__global__ __launch_bounds__(256) void attn_kernel(
    const float* __restrict__ qkv, float* __restrict__ out) {
  extern __shared__ char sm[];
  float2(*QP)[18] = (float2(*)[18])sm;                   //  9216 B
  float2(*KP)[18] = (float2(*)[18])(sm + 9216);          //  9216 B
  float2(*VP)[35] = (float2(*)[35])(sm + 18432);         //  8960 B (V^T, d-major)
  float(*SP)[68] = (float(*)[68])(sm + 27392);           // 17408 B
  float2(*PP)[33] = (float2(*)[33])(sm + 44800);         // 16896 B
  float* cfs = (float*)(sm + 61696);                     //   256 B
  float* lfin = (float*)(sm + 61952);                    //   256 B

  const int tid = threadIdx.x;
  const int bh = blockIdx.y;
  const int b = bh >> 3;
  const int h = bh & 7;
  const int q0 = blockIdx.x * BQ;
  const float scale = 0.17677669529663687f;

  const int r64 = tid >> 2;
  const int dc = (tid & 3) << 3;
  const int pc = dc >> 1;

  const int lane = tid & 31;
  const int warp = tid >> 5;
  const int gid = lane >> 2;
  const int tg = lane & 3;
  const int m0w = (warp >> 1) * 16;  // QK map
  const int n0w = (warp & 1) * 32;
  const int mg = warp >> 2;          // AV map
  const int ng = warp & 3;

  const int tx = tid & 15;
  const int ty = tid >> 4;

  // Q tile once: scale, split, pack.
  {
    const float* qb = qkv + (size_t)(b * SEQ + q0 + r64) * 768 + h * 32 + dc;
    float4 q0v = *(const float4*)qb;
    float4 q1v = *(const float4*)(qb + 4);
    float qv[8] = {q0v.x * scale, q0v.y * scale, q0v.z * scale, q0v.w * scale,
                   q1v.x * scale, q1v.y * scale, q1v.z * scale, q1v.w * scale};
#pragma unroll
    for (int c = 0; c < 4; c++) {
      uint32_t hp, lp;
      SPLIT_PAIR(qv[2 * c], qv[2 * c + 1], hp, lp);
      QP[r64][pc + c] = make_float2(__uint_as_float(hp), __uint_as_float(lp));
    }
  }

  float m_i[4], l_i[4];
#pragma unroll
  for (int i = 0; i < 4; i++) { m_i[i] = -INFINITY; l_i[i] = 0.f; }
  float Oa[2][4];
#pragma unroll
  for (int mt = 0; mt < 2; mt++)
#pragma unroll
    for (int r = 0; r < 4; r++) Oa[mt][r] = 0.f;

  for (int kt = 0; kt < SEQ / BKT; kt++) {
    const int k0 = kt * BKT;
    __syncthreads();  // previous consumers of KP/VP/SP/PP/cfs done
    {
      const float* kb =
          qkv + (size_t)(b * SEQ + k0 + r64) * 768 + 256 + h * 32 + dc;
      float4 k0v = *(const float4*)kb;
      float4 k1v = *(const float4*)(kb + 4);
      float kv[8] = {k0v.x, k0v.y, k0v.z, k0v.w, k1v.x, k1v.y, k1v.z, k1v.w};
#pragma unroll
      for (int c = 0; c < 4; c++) {
        uint32_t hp, lp;
        SPLIT_PAIR(kv[2 * c], kv[2 * c + 1], hp, lp);
        KP[r64][pc + c] = make_float2(__uint_as_float(hp), __uint_as_float(lp));
      }
      // V: load [j][d], pair j with j^1 via lane^4 shuffle, store VP[d][j/2].
      const float* vb = kb + 256;
      float4 v0 = *(const float4*)vb;
      float4 v1 = *(const float4*)(vb + 4);
      float vv[8] = {v0.x, v0.y, v0.z, v0.w, v1.x, v1.y, v1.z, v1.w};
      float pv[8];
#pragma unroll
      for (int i = 0; i < 8; i++)
        pv[i] = __shfl_xor_sync(0xffffffffu, vv[i], 4);
      const int jp = r64 >> 1;
      if ((r64 & 1) == 0) {
#pragma unroll
        for (int i = 0; i < 4; i++) {
          uint32_t hp, lp;
          SPLIT_PAIR(vv[i], pv[i], hp, lp);
          VP[dc + i][jp] =
              make_float2(__uint_as_float(hp), __uint_as_float(lp));
        }
      } else {
#pragma unroll
        for (int i = 4; i < 8; i++) {
          uint32_t hp, lp;
          SPLIT_PAIR(pv[i], vv[i], hp, lp);
          VP[dc + i][jp] =
              make_float2(__uint_as_float(hp), __uint_as_float(lp));
        }
      }
    }
    __syncthreads();

    // ---- QK^T via mma (R14, proven) ----
    {
      float acc[4][4];
#pragma unroll
      for (int nt = 0; nt < 4; nt++)
#pragma unroll
        for (int r = 0; r < 4; r++) acc[nt][r] = 0.f;
#pragma unroll
      for (int s = 0; s < 2; s++) {
        uint32_t aH[4], aL[4];
        {
          float2 a00 = QP[m0w + gid][tg + 8 * s];
          float2 a10 = QP[m0w + gid + 8][tg + 8 * s];
          float2 a01 = QP[m0w + gid][tg + 4 + 8 * s];
          float2 a11 = QP[m0w + gid + 8][tg + 4 + 8 * s];
          aH[0] = __float_as_uint(a00.x); aH[1] = __float_as_uint(a10.x);
          aH[2] = __float_as_uint(a01.x); aH[3] = __float_as_uint(a11.x);
          aL[0] = __float_as_uint(a00.y); aL[1] = __float_as_uint(a10.y);
          aL[2] = __float_as_uint(a01.y); aL[3] = __float_as_uint(a11.y);
        }
        uint32_t bH[4][2], bL[4][2];
#pragma unroll
        for (int nt = 0; nt < 4; nt++) {
          float2 k0p = KP[n0w + nt * 8 + gid][tg + 8 * s];
          float2 k1p = KP[n0w + nt * 8 + gid][tg + 4 + 8 * s];
          bH[nt][0] = __float_as_uint(k0p.x);
          bH[nt][1] = __float_as_uint(k1p.x);
          bL[nt][0] = __float_as_uint(k0p.y);
          bL[nt][1] = __float_as_uint(k1p.y);
        }
#pragma unroll
        for (int nt = 0; nt < 4; nt++) mma_bf16(acc[nt], aH, bH[nt]);
#pragma unroll
        for (int nt = 0; nt < 4; nt++) mma_bf16(acc[nt], aH, bL[nt]);
#pragma unroll
        for (int nt = 0; nt < 4; nt++) mma_bf16(acc[nt], aL, bH[nt]);
      }
#pragma unroll
      for (int nt = 0; nt < 4; nt++) {
        const int col = n0w + nt * 8 + 2 * tg;
        *(float2*)&SP[m0w + gid][col] = make_float2(acc[nt][0], acc[nt][1]);
        *(float2*)&SP[m0w + gid + 8][col] = make_float2(acc[nt][2], acc[nt][3]);
      }
    }
    __syncthreads();

    // ---- softmax (fp32) -> packed probs PP + cfs ----
    {
      float s4[4][4];
#pragma unroll
      for (int i = 0; i < 4; i++) {
        float4 v = *(const float4*)&SP[ty * 4 + i][tx * 4];
        s4[i][0] = v.x; s4[i][1] = v.y; s4[i][2] = v.z; s4[i][3] = v.w;
      }
      float cf_i[4];
#pragma unroll
      for (int i = 0; i < 4; i++) {
        float lm = fmaxf(fmaxf(s4[i][0], s4[i][1]), fmaxf(s4[i][2], s4[i][3]));
#pragma unroll
        for (int o = 8; o > 0; o >>= 1)
          lm = fmaxf(lm, __shfl_xor_sync(0xffffffffu, lm, o));
        float mn = fmaxf(m_i[i], lm);
        cf_i[i] = __expf(m_i[i] - mn);
        m_i[i] = mn;
        float p0 = __expf(s4[i][0] - mn);
        float p1 = __expf(s4[i][1] - mn);
        float p2 = __expf(s4[i][2] - mn);
        float p3 = __expf(s4[i][3] - mn);
        uint32_t hp0, lp0, hp1, lp1;
        SPLIT_PAIR(p0, p1, hp0, lp0);
        SPLIT_PAIR(p2, p3, hp1, lp1);
        const int q = ty * 4 + i;
        PP[q][2 * tx] =
            make_float2(__uint_as_float(hp0), __uint_as_float(lp0));
        PP[q][2 * tx + 1] =
            make_float2(__uint_as_float(hp1), __uint_as_float(lp1));
        float ps = p0 + p1 + p2 + p3;
#pragma unroll
        for (int o = 8; o > 0; o >>= 1)
          ps += __shfl_xor_sync(0xffffffffu, ps, o);
        l_i[i] = l_i[i] * cf_i[i] + ps;
      }
      if (tx == 0) {
#pragma unroll
        for (int i = 0; i < 4; i++) cfs[ty * 4 + i] = cf_i[i];
      }
    }
    __syncthreads();

    // ---- AV via mma: O[64][32] += P[64][64] V[64][32] ----
    {
#pragma unroll
      for (int mt = 0; mt < 2; mt++) {
        const int row = mg * 32 + mt * 16 + gid;
        float c0 = cfs[row], c1 = cfs[row + 8];
        Oa[mt][0] *= c0; Oa[mt][1] *= c0;
        Oa[mt][2] *= c1; Oa[mt][3] *= c1;
      }
#pragma unroll
      for (int s = 0; s < 4; s++) {
        uint32_t bH[2], bL[2];
        {
          float2 b0p = VP[ng * 8 + gid][s * 8 + tg];
          float2 b1p = VP[ng * 8 + gid][s * 8 + tg + 4];
          bH[0] = __float_as_uint(b0p.x); bH[1] = __float_as_uint(b1p.x);
          bL[0] = __float_as_uint(b0p.y); bL[1] = __float_as_uint(b1p.y);
        }
        uint32_t aH[2][4], aL[2][4];
#pragma unroll
        for (int mt = 0; mt < 2; mt++) {
          const int row = mg * 32 + mt * 16 + gid;
          float2 p00 = PP[row][s * 8 + tg];
          float2 p10 = PP[row + 8][s * 8 + tg];
          float2 p01 = PP[row][s * 8 + tg + 4];
          float2 p11 = PP[row + 8][s * 8 + tg + 4];
          aH[mt][0] = __float_as_uint(p00.x);
          aH[mt][1] = __float_as_uint(p10.x);
          aH[mt][2] = __float_as_uint(p01.x);
          aH[mt][3] = __float_as_uint(p11.x);
          aL[mt][0] = __float_as_uint(p00.y);
          aL[mt][1] = __float_as_uint(p10.y);
          aL[mt][2] = __float_as_uint(p01.y);
          aL[mt][3] = __float_as_uint(p11.y);
        }
#pragma unroll
        for (int mt = 0; mt < 2; mt++) mma_bf16(Oa[mt], aH[mt], bH);
#pragma unroll
        for (int mt = 0; mt < 2; mt++) mma_bf16(Oa[mt], aH[mt], bL);
#pragma unroll
        for (int mt = 0; mt < 2; mt++) mma_bf16(Oa[mt], aL[mt], bH);
      }
    }
  }

  if (tx == 0) {
#pragma unroll
    for (int i = 0; i < 4; i++) lfin[ty * 4 + i] = l_i[i];
  }
  __syncthreads();

#pragma unroll
  for (int mt = 0; mt < 2; mt++) {
    const int row = mg * 32 + mt * 16 + gid;
    const float inv0 = 1.0f / lfin[row];
    const float inv1 = 1.0f / lfin[row + 8];
    const int col = h * 32 + ng * 8 + 2 * tg;
    *(float2*)&out[(size_t)(b * SEQ + q0 + row) * D_MODEL + col] =
        make_float2(Oa[mt][0] * inv0, Oa[mt][1] * inv0);
    *(float2*)&out[(size_t)(b * SEQ + q0 + row + 8) * D_MODEL + col] =
        make_float2(Oa[mt][2] * inv1, Oa[mt][3] * inv1);
  }
}

// ---------------------------------------------------------------------------
// Launch
// ---------------------------------------------------------------------------
extern "C" void kernel_launch(void* const* d_in, const int* in_sizes, int n_in,
                              void* d_out, int out_size) {
  const float* x         = (const float*)d_in[0];
  const float* tok_w     = (const float*)d_in[1];
  const float* tok_b     = (const float*)d_in[2];
  const float* tnorm_g   = (const float*)d_in[3];
  const float* tnorm_b   = (const float*)d_in[4];
  const float* in_proj_w = (const float*)d_in[5];
  const float* in_proj_b = (const float*)d_in[6];
  const float* out_w     = (const float*)d_in[7];
  const float* out_b     = (const float*)d_in[8];
  const float* ln1_g     = (const float*)d_in[9];
  const float* ln1_b     = (const float*)d_in[10];
  const float* ln2_g     = (const float*)d_in[11];
  const float* ln2_b     = (const float*)d_in[12];
  const float* lin1_w    = (const float*)d_in[13];
  const float* lin1_b    = (const float*)d_in[14];
  const float* lin2_w    = (const float*)d_in[15];
  const float* lin2_b    = (const float*)d_in[16];
  const float* fnorm_g   = (const float*)d_in[17];
  const float* fnorm_b   = (const float*)d_in[18];
  float* out = (float*)d_out;

  float *y, *h, *qkv, *att, *ff;
  float2 *st, *rope;
  cudaGetSymbolAddress((void**)&y, g_y);
  cudaGetSymbolAddress((void**)&h, g_h);
  cudaGetSymbolAddress((void**)&qkv, g_qkv);
  cudaGetSymbolAddress((void**)&att, g_att);
  cudaGetSymbolAddress((void**)&ff, g_ff);
  cudaGetSymbolAddress((void**)&st, g_stats);
  cudaGetSymbolAddress((void**)&rope, g_rope);

  const int M = M_ROWS;
  const int SB = GEMM_SMEM_BYTES;
  cudaFuncSetAttribute(gemm_kernel<false, false, false, false>,
                       cudaFuncAttributeMaxDynamicSharedMemorySize, SB);
  cudaFuncSetAttribute(gemm_kernel<true, false, false, true>,
                       cudaFuncAttributeMaxDynamicSharedMemorySize, SB);
  cudaFuncSetAttribute(gemm_kernel<false, false, true, false>,
                       cudaFuncAttributeMaxDynamicSharedMemorySize, SB);
  cudaFuncSetAttribute(gemm_kernel<true, true, false, false>,
                       cudaFuncAttributeMaxDynamicSharedMemorySize, SB);
  cudaFuncSetAttribute(attn_kernel,
                       cudaFuncAttributeMaxDynamicSharedMemorySize,
                       ATTN_SMEM_BYTES);

  dim3 blk(256);

  rope_table_kernel<<<SEQ * 16 / 256, blk>>>(rope);

  gemm_kernel<false, false, false, false><<<dim3(2, M / 128), blk, SB>>>(
      x, tok_w, tok_b, nullptr, nullptr, nullptr, nullptr, nullptr, y, M,
      D_MODEL, T_IN);
  ln_kernel<<<M, blk>>>(y, tnorm_g, tnorm_b, h);

  for (int i = 0; i < N_LAYERS; i++) {
    ln_stats_kernel<<<M / 8, blk>>>(h, st);
    gemm_kernel<true, false, false, true><<<dim3(6, M / 128), blk, SB>>>(
        h, in_proj_w + (size_t)i * 768 * D_MODEL, in_proj_b + i * 768, nullptr,
        st, ln1_g + i * D_MODEL, ln1_b + i * D_MODEL, rope, qkv, M, 768,
        D_MODEL);
    attn_kernel<<<dim3(SEQ / BQ, 16 * N_HEADS), blk, ATTN_SMEM_BYTES>>>(qkv,
                                                                        att);
    gemm_kernel<false, false, true, false><<<dim3(2, M / 128), blk, SB>>>(
        att, out_w + (size_t)i * D_MODEL * D_MODEL, out_b + i * D_MODEL, h,
        nullptr, nullptr, nullptr, nullptr, h, M, D_MODEL, D_MODEL);
    ln_stats_kernel<<<M / 8, blk>>>(h, st);
    gemm_kernel<true, true, false, false><<<dim3(8, M / 128), blk, SB>>>(
        h, lin1_w + (size_t)i * FF_DIM * D_MODEL, lin1_b + i * FF_DIM, nullptr,
        st, ln2_g + i * D_MODEL, ln2_b + i * D_MODEL, nullptr, ff, M, FF_DIM,
        D_MODEL);
    gemm_kernel<false, false, true, false><<<dim3(2, M / 128), blk, SB>>>(
        ff, lin2_w + (size_t)i * D_MODEL * FF_DIM, lin2_b + i * D_MODEL, h,
        nullptr, nullptr, nullptr, nullptr, h, M, D_MODEL, FF_DIM);
  }

  ln_kernel<<<M, blk>>>(h, fnorm_g, fnorm_b, out);
}

// round 16
// speedup vs baseline: 1.0623x; 1.0623x over previous
#include <cuda_runtime.h>
#include <math.h>
#include <stdint.h>

// ---------------------------------------------------------------------------
// iTransformer encoder, round 16: R14 (best, 3822us) + pre-split WEIGHTS for
// the bf16 3-term GEMM. Packed (hi,lo) bf16x2 = 4 B/elem == fp32 footprint,
// so B-side gmem traffic is unchanged while the in-loop B split vanishes.
// Attention = R14 verbatim (QK^T on tensor cores, fp32 softmax/AV).
// B=16, S=1024, T=512, D=256, H=8, DH=32, L=4, FF=1024. M = B*S = 16384.
// ---------------------------------------------------------------------------

#define M_ROWS 16384
#define D_MODEL 256
#define T_IN 512
#define FF_DIM 1024
#define N_HEADS 8
#define DH 32
#define SEQ 1024
#define N_LAYERS 4

__device__ float g_y[M_ROWS * D_MODEL];
__device__ float g_h[M_ROWS * D_MODEL];
__device__ float g_qkv[M_ROWS * 3 * D_MODEL];
__device__ float g_att[M_ROWS * D_MODEL];
__device__ float g_ff[M_ROWS * FF_DIM];
__device__ float2 g_stats[M_ROWS];
__device__ float2 g_rope[SEQ * 16];
// packed split weights: float2 = (hi_pack, lo_pack) per k-pair; 4 B/elem total
#define WOFF_TOK 0
#define WOFF_INPJ 65536
#define WSTR_INPJ 98304
#define WOFF_OUT 458752
#define WSTR_OUT 32768
#define WOFF_L1 589824
#define WSTR_L1 131072
#define WOFF_L2 1114112
#define WSTR_L2 131072
#define WSP_TOTAL 1638400
__device__ float2 g_wsp[WSP_TOTAL];

__device__ __forceinline__ void mma_bf16(float* d, const uint32_t* a,
                                         const uint32_t* b) {
  asm("mma.sync.aligned.m16n8k16.row.col.f32.bf16.bf16.f32 "
      "{%0,%1,%2,%3}, {%4,%5,%6,%7}, {%8,%9}, {%0,%1,%2,%3};\n"
      : "+f"(d[0]), "+f"(d[1]), "+f"(d[2]), "+f"(d[3])
      : "r"(a[0]), "r"(a[1]), "r"(a[2]), "r"(a[3]), "r"(b[0]), "r"(b[1]));
}

// Truncation split (ALL ALU). e0 = even k -> low half, e1 = odd k -> high half.
#define SPLIT_PAIR(e0, e1, hp, lp)                                             \
  {                                                                            \
    uint32_t u0 = __float_as_uint(e0), u1 = __float_as_uint(e1);               \
    float l0 = (e0) - __uint_as_float(u0 & 0xffff0000u);                       \
    float l1 = (e1) - __uint_as_float(u1 & 0xffff0000u);                       \
    hp = __byte_perm(u0, u1, 0x7632);                                          \
    lp = __byte_perm(__float_as_uint(l0), __float_as_uint(l1), 0x7632);        \
  }

// ---------------------------------------------------------------------------
// Weight split: X[R][K] -> out[(r*(K/8)+s)*4 + c] = (hi_pack, lo_pack) for
// pair (k = 8s+2c, 8s+2c+1). Output bytes = input bytes / 2.
// ---------------------------------------------------------------------------
__global__ __launch_bounds__(256) void split_w_kernel(
    const float* __restrict__ X, float2* __restrict__ out, int total_slices) {
  const int idx = blockIdx.x * 256 + threadIdx.x;
  if (idx >= total_slices) return;
  float4 x0 = *(const float4*)(X + (size_t)idx * 8);
  float4 x1 = *(const float4*)(X + (size_t)idx * 8 + 4);
  float v[8] = {x0.x, x0.y, x0.z, x0.w, x1.x, x1.y, x1.z, x1.w};
  float2* o = out + (size_t)idx * 4;
#pragma unroll
  for (int c = 0; c < 4; c++) {
    uint32_t hp, lp;
    SPLIT_PAIR(v[2 * c], v[2 * c + 1], hp, lp);
    o[c] = make_float2(__uint_as_float(hp), __uint_as_float(lp));
  }
}

// ---------------------------------------------------------------------------
// Per-row LN stats.
// ---------------------------------------------------------------------------
__global__ __launch_bounds__(256) void ln_stats_kernel(
    const float* __restrict__ in, float2* __restrict__ st) {
  const int warp = threadIdx.x >> 5;
  const int lane = threadIdx.x & 31;
  const int row = blockIdx.x * 8 + warp;
  const float* p = in + (size_t)row * D_MODEL + lane * 8;
  float4 v0 = *(const float4*)p;
  float4 v1 = *(const float4*)(p + 4);
  float v[8] = {v0.x, v0.y, v0.z, v0.w, v1.x, v1.y, v1.z, v1.w};
  float s = 0.f;
#pragma unroll
  for (int i = 0; i < 8; i++) s += v[i];
#pragma unroll
  for (int o = 16; o > 0; o >>= 1) s += __shfl_xor_sync(0xffffffffu, s, o);
  float mean = s * (1.0f / 256.0f);
  float s2 = 0.f;
#pragma unroll
  for (int i = 0; i < 8; i++) {
    float d = v[i] - mean;
    s2 += d * d;
  }
#pragma unroll
  for (int o = 16; o > 0; o >>= 1) s2 += __shfl_xor_sync(0xffffffffu, s2, o);
  float var = s2 * (1.0f / 256.0f);
  if (lane == 0) st[row] = make_float2(mean, rsqrtf(var + 1e-5f));
}

// ---------------------------------------------------------------------------
// RoPE table.
// ---------------------------------------------------------------------------
__global__ __launch_bounds__(256) void rope_table_kernel(
    float2* __restrict__ tab) {
  int idx = blockIdx.x * 256 + threadIdx.x;
  int j = idx & 15;
  int s = idx >> 4;
  float inv_freq = 1.0f / powf(10000.0f, (float)j * 0.0625f);
  float c, sn;
  sincosf((float)s * inv_freq, &c, &sn);
  tab[idx] = make_float2(c, sn);
}

// ---------------------------------------------------------------------------
// 3-term BF16x2 GEMM, weights pre-split. A split in-loop (LN fused).
// Block 128x128xK16, 8 warps, m16n8k16, term-major HH/HL/LH.
// ---------------------------------------------------------------------------
#define GEMM_SMEM_BYTES (2 * 2 * 128 * 4 * 8 * 2)

#define LN_APPLY()                                                             \
  do {                                                                         \
    if (LNA) {                                                                 \
      const float* gp = lng + k0 + lsl * 8;                                    \
      const float* bp = lnb + k0 + lsl * 8;                                    \
      float4 gg0 = *(const float4*)gp, gg1 = *(const float4*)(gp + 4);         \
      float4 bb0 = *(const float4*)bp, bb1 = *(const float4*)(bp + 4);         \
      va0.x = fmaf((va0.x - mu) * rsd, gg0.x, bb0.x);                          \
      va0.y = fmaf((va0.y - mu) * rsd, gg0.y, bb0.y);                          \
      va0.z = fmaf((va0.z - mu) * rsd, gg0.z, bb0.z);                          \
      va0.w = fmaf((va0.w - mu) * rsd, gg0.w, bb0.w);                          \
      va1.x = fmaf((va1.x - mu) * rsd, gg1.x, bb1.x);                          \
      va1.y = fmaf((va1.y - mu) * rsd, gg1.y, bb1.y);                          \
      va1.z = fmaf((va1.z - mu) * rsd, gg1.z, bb1.z);                          \
      va1.w = fmaf((va1.w - mu) * rsd, gg1.w, bb1.w);                          \
    }                                                                          \
  } while (0)

#define STAGE_STORE(BUF)                                                       \
  do {                                                                         \
    float av[8] = {va0.x, va0.y, va0.z, va0.w, va1.x, va1.y, va1.z, va1.w};    \
    _Pragma("unroll") for (int c = 0; c < 4; c++) {                            \
      uint32_t ah, al;                                                         \
      SPLIT_PAIR(av[2 * c], av[2 * c + 1], ah, al);                            \
      As[BUF][lsl][lrow][c] =                                                  \
          make_float2(__uint_as_float(ah), __uint_as_float(al));               \
    }                                                                          \
    Bs[BUF][lsl][lrow][0] = make_float2(wb01.x, wb01.y);                       \
    Bs[BUF][lsl][lrow][1] = make_float2(wb01.z, wb01.w);                       \
    Bs[BUF][lsl][lrow][2] = make_float2(wb23.x, wb23.y);                       \
    Bs[BUF][lsl][lrow][3] = make_float2(wb23.z, wb23.w);                       \
  } while (0)

#define COMPUTE_STAGE(BUF)                                                     \
  {                                                                            \
    uint32_t bfH[4][2], bfL[4][2];                                             \
    _Pragma("unroll") for (int nt = 0; nt < 4; nt++) {                         \
      const int rw = wn * 32 + nt * 8 + gid;                                   \
      float2 q0 = Bs[BUF][0][rw][tg];                                          \
      float2 q1 = Bs[BUF][1][rw][tg];                                          \
      bfH[nt][0] = __float_as_uint(q0.x); bfH[nt][1] = __float_as_uint(q1.x);  \
      bfL[nt][0] = __float_as_uint(q0.y); bfL[nt][1] = __float_as_uint(q1.y);  \
    }                                                                          \
    _Pragma("unroll") for (int mh = 0; mh < 2; mh++) {                         \
      uint32_t afH[2][4], afL[2][4];                                           \
      _Pragma("unroll") for (int mi = 0; mi < 2; mi++) {                       \
        const int rb = wm * 64 + (mh * 2 + mi) * 16 + gid;                     \
        float2 a00 = As[BUF][0][rb][tg];                                       \
        float2 a01 = As[BUF][0][rb + 8][tg];                                   \
        float2 a10 = As[BUF][1][rb][tg];                                       \
        float2 a11 = As[BUF][1][rb + 8][tg];                                   \
        afH[mi][0] = __float_as_uint(a00.x);                                   \
        afH[mi][1] = __float_as_uint(a01.x);                                   \
        afH[mi][2] = __float_as_uint(a10.x);                                   \
        afH[mi][3] = __float_as_uint(a11.x);                                   \
        afL[mi][0] = __float_as_uint(a00.y);                                   \
        afL[mi][1] = __float_as_uint(a01.y);                                   \
        afL[mi][2] = __float_as_uint(a10.y);                                   \
        afL[mi][3] = __float_as_uint(a11.y);                                   \
      }                                                                        \
      _Pragma("unroll") for (int mi = 0; mi < 2; mi++)                         \
          _Pragma("unroll") for (int nt = 0; nt < 4; nt++)                     \
          mma_bf16(acc[mh * 2 + mi][nt], afH[mi], bfH[nt]);                    \
      _Pragma("unroll") for (int mi = 0; mi < 2; mi++)                         \
          _Pragma("unroll") for (int nt = 0; nt < 4; nt++)                     \
          mma_bf16(acc[mh * 2 + mi][nt], afH[mi], bfL[nt]);                    \
      _Pragma("unroll") for (int mi = 0; mi < 2; mi++)                         \
          _Pragma("unroll") for (int nt = 0; nt < 4; nt++)                     \
          mma_bf16(acc[mh * 2 + mi][nt], afL[mi], bfH[nt]);                    \
    }                                                                          \
  }

template <bool LNA, bool RELU, bool RES, bool ROPE>
__global__ __launch_bounds__(256, 2) void gemm_kernel(
    const float* __restrict__ A, const float2* __restrict__ W2,
    const float* __restrict__ bias, const float* __restrict__ res,
    const float2* __restrict__ stats, const float* __restrict__ lng,
    const float* __restrict__ lnb, const float2* __restrict__ rope,
    float* __restrict__ C, int M, int N, int K) {
  extern __shared__ float2 smem_dyn[];
  typedef float2 (*SmemT)[2][128][4];
  SmemT As = (SmemT)smem_dyn;
  SmemT Bs = (SmemT)(smem_dyn + 2 * 2 * 128 * 4);

  const int tid = threadIdx.x;
  const int lane = tid & 31;
  const int warp = tid >> 5;
  const int wm = warp >> 2;
  const int wn = warp & 3;
  const int gid = lane >> 2;
  const int tg = lane & 3;

  const int m0 = blockIdx.y * 128;
  const int n0 = blockIdx.x * 128;

  const int lrow = tid >> 1;
  const int lsl = tid & 1;

  const float* Ap = A + (size_t)(m0 + lrow) * K + lsl * 8;
  const float2* Wp = W2 + (size_t)(n0 + lrow) * (K >> 1) + lsl * 4;

  float mu = 0.f, rsd = 1.f;
  if (LNA) {
    float2 st = stats[m0 + lrow];
    mu = st.x;
    rsd = st.y;
  }

  float acc[4][4][4];
#pragma unroll
  for (int i = 0; i < 4; i++)
#pragma unroll
    for (int j = 0; j < 4; j++)
#pragma unroll
      for (int r = 0; r < 4; r++) acc[i][j][r] = 0.f;

  {
    const int k0 = 0;
    float4 va0 = *(const float4*)(Ap);
    float4 va1 = *(const float4*)(Ap + 4);
    float4 wb01 = *(const float4*)(Wp);
    float4 wb23 = *(const float4*)(Wp + 2);
    LN_APPLY();
    STAGE_STORE(0);
    (void)k0;
  }
  __syncthreads();

  int buf = 0;
  for (int k0 = 16; k0 < K; k0 += 16) {
    const int woff = k0 >> 1;
    float4 va0 = *(const float4*)(Ap + k0);
    float4 va1 = *(const float4*)(Ap + k0 + 4);
    float4 wb01 = *(const float4*)(Wp + woff);
    float4 wb23 = *(const float4*)(Wp + woff + 2);
    LN_APPLY();
    COMPUTE_STAGE(buf);
    const int nxt = buf ^ 1;
    STAGE_STORE(nxt);
    __syncthreads();
    buf = nxt;
  }
  COMPUTE_STAGE(buf);

  const bool doRot = ROPE && (n0 + wn * 32) < 2 * D_MODEL;

#pragma unroll
  for (int mt = 0; mt < 4; mt++) {
    const int row = m0 + wm * 64 + mt * 16 + gid;
    float4 rr[4];
#pragma unroll
    for (int nt = 0; nt < 4; nt++) {
      const int col = n0 + wn * 32 + nt * 8 + tg * 2;
      float2 bb = *(const float2*)&bias[col];
      rr[nt] = make_float4(acc[mt][nt][0] + bb.x, acc[mt][nt][1] + bb.y,
                           acc[mt][nt][2] + bb.x, acc[mt][nt][3] + bb.y);
    }
    if (doRot) {
      const int s = row & (SEQ - 1);
      const int s8 = s + 8;
#pragma unroll
      for (int p = 0; p < 2; p++) {
        const int j0 = p * 8 + tg * 2;
        float2 c0 = rope[s * 16 + j0];
        float2 c1 = rope[s * 16 + j0 + 1];
        float2 d0 = rope[s8 * 16 + j0];
        float2 d1 = rope[s8 * 16 + j0 + 1];
        float4 a = rr[p], q = rr[p + 2];
        rr[p].x = a.x * c0.x - q.x * c0.y;
        rr[p + 2].x = q.x * c0.x + a.x * c0.y;
        rr[p].y = a.y * c1.x - q.y * c1.y;
        rr[p + 2].y = q.y * c1.x + a.y * c1.y;
        rr[p].z = a.z * d0.x - q.z * d0.y;
        rr[p + 2].z = q.z * d0.x + a.z * d0.y;
        rr[p].w = a.w * d1.x - q.w * d1.y;
        rr[p + 2].w = q.w * d1.x + a.w * d1.y;
      }
    }
#pragma unroll
    for (int nt = 0; nt < 4; nt++) {
      const int col = n0 + wn * 32 + nt * 8 + tg * 2;
      float2 r0 = make_float2(rr[nt].x, rr[nt].y);
      float2 r1 = make_float2(rr[nt].z, rr[nt].w);
      if (RELU) {
        r0.x = fmaxf(r0.x, 0.f); r0.y = fmaxf(r0.y, 0.f);
        r1.x = fmaxf(r1.x, 0.f); r1.y = fmaxf(r1.y, 0.f);
      }
      if (RES) {
        float2 q0 = *(const float2*)&res[(size_t)row * N + col];
        float2 q1 = *(const float2*)&res[(size_t)(row + 8) * N + col];
        r0.x += q0.x; r0.y += q0.y;
        r1.x += q1.x; r1.y += q1.y;
      }
      *(float2*)&C[(size_t)row * N + col] = r0;
      *(float2*)&C[(size_t)(row + 8) * N + col] = r1;
    }
  }
}

// ---------------------------------------------------------------------------
// Full LayerNorm (tokenize + final).
// ---------------------------------------------------------------------------
__global__ __launch_bounds__(256) void ln_kernel(
    const float* __restrict__ in, const float* __restrict__ g,
    const float* __restrict__ b, float* __restrict__ out) {
  const int row = blockIdx.x;
  const int t = threadIdx.x;
  float v = in[(size_t)row * D_MODEL + t];

  float s = v;
#pragma unroll
  for (int o = 16; o > 0; o >>= 1) s += __shfl_xor_sync(0xffffffffu, s, o);
  __shared__ float ws[8];
  __shared__ float ws2[8];
  if ((t & 31) == 0) ws[t >> 5] = s;
  __syncthreads();
  float mean = (ws[0] + ws[1] + ws[2] + ws[3] + ws[4] + ws[5] + ws[6] + ws[7]) *
               (1.0f / 256.0f);
  float d = v - mean;
  float s2 = d * d;
#pragma unroll
  for (int o = 16; o > 0; o >>= 1) s2 += __shfl_xor_sync(0xffffffffu, s2, o);
  if ((t & 31) == 0) ws2[t >> 5] = s2;
  __syncthreads();
  float var = (ws2[0] + ws2[1] + ws2[2] + ws2[3] + ws2[4] + ws2[5] + ws2[6] +
               ws2[7]) * (1.0f / 256.0f);
  out[(size_t)row * D_MODEL + t] = d * rsqrtf(var + 1e-5f) * g[t] + b[t];
}

// ---------------------------------------------------------------------------
// Attention (R14, proven): QK^T on bf16 tensor cores, fp32 softmax + AV.
// ---------------------------------------------------------------------------
#define BQ 64
#define BKT 64
__global__ __launch_bounds__(256) void attn_kernel(
    const float* __restrict__ qkv, float* __restrict__ out) {
  __shared__ float2 QP[BQ][18];
  __shared__ float2 KP[BKT][18];
  __shared__ float Vs[BKT][36];
  __shared__ float SP[BQ][68];

  const int tid = threadIdx.x;
  const int bh = blockIdx.y;
  const int b = bh >> 3;
  const int h = bh & 7;
  const int q0 = blockIdx.x * BQ;
  const float scale = 0.17677669529663687f;

  const int r64 = tid >> 2;
  const int dc = (tid & 3) << 3;
  const int pc = dc >> 1;

  const int lane = tid & 31;
  const int warp = tid >> 5;
  const int gid = lane >> 2;
  const int tg = lane & 3;
  const int m0w = (warp >> 1) * 16;
  const int n0w = (warp & 1) * 32;

  const int tx = tid & 15;
  const int ty = tid >> 4;
  const int jh = tx >> 3;
  const int dm = tx & 7;

  {
    const float* qb = qkv + (size_t)(b * SEQ + q0 + r64) * 768 + h * 32 + dc;
    float4 q0v = *(const float4*)qb;
    float4 q1v = *(const float4*)(qb + 4);
    float qv[8] = {q0v.x * scale, q0v.y * scale, q0v.z * scale, q0v.w * scale,
                   q1v.x * scale, q1v.y * scale, q1v.z * scale, q1v.w * scale};
#pragma unroll
    for (int c = 0; c < 4; c++) {
      uint32_t hp, lp;
      SPLIT_PAIR(qv[2 * c], qv[2 * c + 1], hp, lp);
      QP[r64][pc + c] = make_float2(__uint_as_float(hp), __uint_as_float(lp));
    }
  }

  float m_i[4], l_i[4];
#pragma unroll
  for (int i = 0; i < 4; i++) { m_i[i] = -INFINITY; l_i[i] = 0.f; }
  float O[4][4];
#pragma unroll
  for (int i = 0; i < 4; i++)
#pragma unroll
    for (int d = 0; d < 4; d++) O[i][d] = 0.f;

  for (int kt = 0; kt < SEQ / BKT; kt++) {
    const int k0 = kt * BKT;
    __syncthreads();
    {
      const float* kb =
          qkv + (size_t)(b * SEQ + k0 + r64) * 768 + 256 + h * 32 + dc;
      float4 k0v = *(const float4*)kb;
      float4 k1v = *(const float4*)(kb + 4);
      float kv[8] = {k0v.x, k0v.y, k0v.z, k0v.w, k1v.x, k1v.y, k1v.z, k1v.w};
#pragma unroll
      for (int c = 0; c < 4; c++) {
        uint32_t hp, lp;
        SPLIT_PAIR(kv[2 * c], kv[2 * c + 1], hp, lp);
        KP[r64][pc + c] = make_float2(__uint_as_float(hp), __uint_as_float(lp));
      }
      const float* vb = kb + 256;
      *(float4*)&Vs[r64][dc] = *(const float4*)vb;
      *(float4*)&Vs[r64][dc + 4] = *(const float4*)(vb + 4);
    }
    __syncthreads();

    {
      float acc[4][4];
#pragma unroll
      for (int nt = 0; nt < 4; nt++)
#pragma unroll
        for (int r = 0; r < 4; r++) acc[nt][r] = 0.f;
#pragma unroll
      for (int s = 0; s < 2; s++) {
        uint32_t aH[4], aL[4];
        {
          float2 a00 = QP[m0w + gid][tg + 8 * s];
          float2 a10 = QP[m0w + gid + 8][tg + 8 * s];
          float2 a01 = QP[m0w + gid][tg + 4 + 8 * s];
          float2 a11 = QP[m0w + gid + 8][tg + 4 + 8 * s];
          aH[0] = __float_as_uint(a00.x); aH[1] = __float_as_uint(a10.x);
          aH[2] = __float_as_uint(a01.x); aH[3] = __float_as_uint(a11.x);
          aL[0] = __float_as_uint(a00.y); aL[1] = __float_as_uint(a10.y);
          aL[2] = __float_as_uint(a01.y); aL[3] = __float_as_uint(a11.y);
        }
        uint32_t bH[4][2], bL[4][2];
#pragma unroll
        for (int nt = 0; nt < 4; nt++) {
          float2 k0p = KP[n0w + nt * 8 + gid][tg + 8 * s];
          float2 k1p = KP[n0w + nt * 8 + gid][tg + 4 + 8 * s];
          bH[nt][0] = __float_as_uint(k0p.x);
          bH[nt][1] = __float_as_uint(k1p.x);
          bL[nt][0] = __float_as_uint(k0p.y);
          bL[nt][1] = __float_as_uint(k1p.y);
        }
#pragma unroll
        for (int nt = 0; nt < 4; nt++) mma_bf16(acc[nt], aH, bH[nt]);
#pragma unroll
        for (int nt = 0; nt < 4; nt++) mma_bf16(acc[nt], aH, bL[nt]);
#pragma unroll
        for (int nt = 0; nt < 4; nt++) mma_bf16(acc[nt], aL, bH[nt]);
      }
#pragma unroll
      for (int nt = 0; nt < 4; nt++) {
        const int col = n0w + nt * 8 + 2 * tg;
        *(float2*)&SP[m0w + gid][col] = make_float2(acc[nt][0], acc[nt][1]);
        *(float2*)&SP[m0w + gid + 8][col] = make_float2(acc[nt][2], acc[nt][3]);
      }
    }
    __syncthreads();

    float s4[4][4];
#pragma unroll
    for (int i = 0; i < 4; i++) {
      float4 v = *(const float4*)&SP[ty * 4 + i][tx * 4];
      s4[i][0] = v.x; s4[i][1] = v.y; s4[i][2] = v.z; s4[i][3] = v.w;
    }
    __syncthreads();

    const int swz = (ty ^ (tx >> 1)) * 4;
    float cf_i[4];
#pragma unroll
    for (int i = 0; i < 4; i++) {
      float lm = fmaxf(fmaxf(s4[i][0], s4[i][1]), fmaxf(s4[i][2], s4[i][3]));
#pragma unroll
      for (int o = 8; o > 0; o >>= 1)
        lm = fmaxf(lm, __shfl_xor_sync(0xffffffffu, lm, o));
      float mn = fmaxf(m_i[i], lm);
      cf_i[i] = __expf(m_i[i] - mn);
      m_i[i] = mn;
      float ps = 0.f;
#pragma unroll
      for (int j = 0; j < 4; j++) {
        float p = __expf(s4[i][j] - mn);
        SP[tx * 4 + j][swz + i] = p;
        ps += p;
      }
#pragma unroll
      for (int o = 8; o > 0; o >>= 1)
        ps += __shfl_xor_sync(0xffffffffu, ps, o);
      l_i[i] = l_i[i] * cf_i[i] + ps;
    }
#pragma unroll
    for (int i = 0; i < 4; i++)
#pragma unroll
      for (int d = 0; d < 4; d++) O[i][d] *= cf_i[i];
    __syncthreads();

#pragma unroll
    for (int jblk = 0; jblk < 4; jblk++) {
      const int c4 = (ty ^ ((jh * 4 + jblk) & 7)) * 4;
#pragma unroll
      for (int jj = 0; jj < 8; jj++) {
        const int j = jh * 32 + jblk * 8 + jj;
        float4 p4 = *(const float4*)&SP[j][c4];
        float4 v4 = *(const float4*)&Vs[j][dm * 4];
        float pa[4] = {p4.x, p4.y, p4.z, p4.w};
        float va[4] = {v4.x, v4.y, v4.z, v4.w};
#pragma unroll
        for (int i = 0; i < 4; i++)
#pragma unroll
          for (int d = 0; d < 4; d++)
            O[i][d] = fmaf(pa[i], va[d], O[i][d]);
      }
    }
  }

#pragma unroll
  for (int i = 0; i < 4; i++)
#pragma unroll
    for (int d = 0; d < 4; d++)
      O[i][d] += __shfl_xor_sync(0xffffffffu, O[i][d], 8);

  if (jh == 0) {
#pragma unroll
    for (int i = 0; i < 4; i++) {
      const float inv = 1.0f / l_i[i];
      float4 r = make_float4(O[i][0] * inv, O[i][1] * inv, O[i][2] * inv,
                             O[i][3] * inv);
      *(float4*)&out[(size_t)(b * SEQ + q0 + ty * 4 + i) * D_MODEL + h * 32 +
                     dm * 4] = r;
    }
  }
}

// ---------------------------------------------------------------------------
// Launch
// ---------------------------------------------------------------------------
extern "C" void kernel_launch(void* const* d_in, const int* in_sizes, int n_in,
                              void* d_out, int out_size) {
  const float* x         = (const float*)d_in[0];
  const float* tok_w     = (const float*)d_in[1];
  const float* tok_b     = (const float*)d_in[2];
  const float* tnorm_g   = (const float*)d_in[3];
  const float* tnorm_b   = (const float*)d_in[4];
  const float* in_proj_w = (const float*)d_in[5];
  const float* in_proj_b = (const float*)d_in[6];
  const float* out_w     = (const float*)d_in[7];
  const float* out_b     = (const float*)d_in[8];
  const float* ln1_g     = (const float*)d_in[9];
  const float* ln1_b     = (const float*)d_in[10];
  const float* ln2_g     = (const float*)d_in[11];
  const float* ln2_b     = (const float*)d_in[12];
  const float* lin1_w    = (const float*)d_in[13];
  const float* lin1_b    = (const float*)d_in[14];
  const float* lin2_w    = (const float*)d_in[15];
  const float* lin2_b    = (const float*)d_in[16];
  const float* fnorm_g   = (const float*)d_in[17];
  const float* fnorm_b   = (const float*)d_in[18];
  float* out = (float*)d_out;

  float *y, *h, *qkv, *att, *ff;
  float2 *st, *rope, *wsp;
  cudaGetSymbolAddress((void**)&y, g_y);
  cudaGetSymbolAddress((void**)&h, g_h);
  cudaGetSymbolAddress((void**)&qkv, g_qkv);
  cudaGetSymbolAddress((void**)&att, g_att);
  cudaGetSymbolAddress((void**)&ff, g_ff);
  cudaGetSymbolAddress((void**)&st, g_stats);
  cudaGetSymbolAddress((void**)&rope, g_rope);
  cudaGetSymbolAddress((void**)&wsp, g_wsp);

  const int M = M_ROWS;
  const int SB = GEMM_SMEM_BYTES;
  cudaFuncSetAttribute(gemm_kernel<false, false, false, false>,
                       cudaFuncAttributeMaxDynamicSharedMemorySize, SB);
  cudaFuncSetAttribute(gemm_kernel<true, false, false, true>,
                       cudaFuncAttributeMaxDynamicSharedMemorySize, SB);
  cudaFuncSetAttribute(gemm_kernel<false, false, true, false>,
                       cudaFuncAttributeMaxDynamicSharedMemorySize, SB);
  cudaFuncSetAttribute(gemm_kernel<true, true, false, false>,
                       cudaFuncAttributeMaxDynamicSharedMemorySize, SB);

  dim3 blk(256);
#define SPLITW(SRC, DST, R, K)                                           \
  split_w_kernel<<<((R) * ((K) / 8) + 255) / 256, blk>>>(                \
      SRC, DST, (R) * ((K) / 8))

  SPLITW(tok_w, wsp + WOFF_TOK, 256, 512);
  SPLITW(in_proj_w, wsp + WOFF_INPJ, 4 * 768, 256);
  SPLITW(out_w, wsp + WOFF_OUT, 4 * 256, 256);
  SPLITW(lin1_w, wsp + WOFF_L1, 4 * 1024, 256);
  SPLITW(lin2_w, wsp + WOFF_L2, 4 * 256, 1024);
  rope_table_kernel<<<SEQ * 16 / 256, blk>>>(rope);

  gemm_kernel<false, false, false, false><<<dim3(2, M / 128), blk, SB>>>(
      x, wsp + WOFF_TOK, tok_b, nullptr, nullptr, nullptr, nullptr, nullptr, y,
      M, D_MODEL, T_IN);
  ln_kernel<<<M, blk>>>(y, tnorm_g, tnorm_b, h);

  for (int i = 0; i < N_LAYERS; i++) {
    ln_stats_kernel<<<M / 8, blk>>>(h, st);
    gemm_kernel<true, false, false, true><<<dim3(6, M / 128), blk, SB>>>(
        h, wsp + WOFF_INPJ + (size_t)i * WSTR_INPJ, in_proj_b + i * 768,
        nullptr, st, ln1_g + i * D_MODEL, ln1_b + i * D_MODEL, rope, qkv, M,
        768, D_MODEL);
    attn_kernel<<<dim3(SEQ / BQ, 16 * N_HEADS), blk>>>(qkv, att);
    gemm_kernel<false, false, true, false><<<dim3(2, M / 128), blk, SB>>>(
        att, wsp + WOFF_OUT + (size_t)i * WSTR_OUT, out_b + i * D_MODEL, h,
        nullptr, nullptr, nullptr, nullptr, h, M, D_MODEL, D_MODEL);
    ln_stats_kernel<<<M / 8, blk>>>(h, st);
    gemm_kernel<true, true, false, false><<<dim3(8, M / 128), blk, SB>>>(
        h, wsp + WOFF_L1 + (size_t)i * WSTR_L1, lin1_b + i * FF_DIM, nullptr,
        st, ln2_g + i * D_MODEL, ln2_b + i * D_MODEL, nullptr, ff, M, FF_DIM,
        D_MODEL);
    gemm_kernel<false, false, true, false><<<dim3(2, M / 128), blk, SB>>>(
        ff, wsp + WOFF_L2 + (size_t)i * WSTR_L2, lin2_b + i * D_MODEL, h,
        nullptr, nullptr, nullptr, nullptr, h, M, D_MODEL, FF_DIM);
  }

  ln_kernel<<<M, blk>>>(h, fnorm_g, fnorm_b, out);
}

// round 17
// speedup vs baseline: 1.1729x; 1.1040x over previous
#include <cuda_runtime.h>
#include <math.h>
#include <stdint.h>

// ---------------------------------------------------------------------------
// iTransformer encoder, round 17: R14 GEMM (best) + R15 attention (QK^T and
// AV on bf16 tensor cores) with CONFLICT-FREE smem strides (PP/VP padded to
// 36 float2: row stride 72 words = 8 mod 32 -> phase-clean LDS.64).
// B=16, S=1024, T=512, D=256, H=8, DH=32, L=4, FF=1024. M = B*S = 16384.
// ---------------------------------------------------------------------------

#define M_ROWS 16384
#define D_MODEL 256
#define T_IN 512
#define FF_DIM 1024
#define N_HEADS 8
#define DH 32
#define SEQ 1024
#define N_LAYERS 4

__device__ float g_y[M_ROWS * D_MODEL];
__device__ float g_h[M_ROWS * D_MODEL];
__device__ float g_qkv[M_ROWS * 3 * D_MODEL];
__device__ float g_att[M_ROWS * D_MODEL];
__device__ float g_ff[M_ROWS * FF_DIM];
__device__ float2 g_stats[M_ROWS];
__device__ float2 g_rope[SEQ * 16];

__device__ __forceinline__ void mma_bf16(float* d, const uint32_t* a,
                                         const uint32_t* b) {
  asm("mma.sync.aligned.m16n8k16.row.col.f32.bf16.bf16.f32 "
      "{%0,%1,%2,%3}, {%4,%5,%6,%7}, {%8,%9}, {%0,%1,%2,%3};\n"
      : "+f"(d[0]), "+f"(d[1]), "+f"(d[2]), "+f"(d[3])
      : "r"(a[0]), "r"(a[1]), "r"(a[2]), "r"(a[3]), "r"(b[0]), "r"(b[1]));
}

// Truncation split (ALL ALU). e0 = even k -> low half, e1 = odd k -> high half.
#define SPLIT_PAIR(e0, e1, hp, lp)                                             \
  {                                                                            \
    uint32_t u0 = __float_as_uint(e0), u1 = __float_as_uint(e1);               \
    float l0 = (e0) - __uint_as_float(u0 & 0xffff0000u);                       \
    float l1 = (e1) - __uint_as_float(u1 & 0xffff0000u);                       \
    hp = __byte_perm(u0, u1, 0x7632);                                          \
    lp = __byte_perm(__float_as_uint(l0), __float_as_uint(l1), 0x7632);        \
  }

// ---------------------------------------------------------------------------
// Per-row LN stats.
// ---------------------------------------------------------------------------
__global__ __launch_bounds__(256) void ln_stats_kernel(
    const float* __restrict__ in, float2* __restrict__ st) {
  const int warp = threadIdx.x >> 5;
  const int lane = threadIdx.x & 31;
  const int row = blockIdx.x * 8 + warp;
  const float* p = in + (size_t)row * D_MODEL + lane * 8;
  float4 v0 = *(const float4*)p;
  float4 v1 = *(const float4*)(p + 4);
  float v[8] = {v0.x, v0.y, v0.z, v0.w, v1.x, v1.y, v1.z, v1.w};
  float s = 0.f;
#pragma unroll
  for (int i = 0; i < 8; i++) s += v[i];
#pragma unroll
  for (int o = 16; o > 0; o >>= 1) s += __shfl_xor_sync(0xffffffffu, s, o);
  float mean = s * (1.0f / 256.0f);
  float s2 = 0.f;
#pragma unroll
  for (int i = 0; i < 8; i++) {
    float d = v[i] - mean;
    s2 += d * d;
  }
#pragma unroll
  for (int o = 16; o > 0; o >>= 1) s2 += __shfl_xor_sync(0xffffffffu, s2, o);
  float var = s2 * (1.0f / 256.0f);
  if (lane == 0) st[row] = make_float2(mean, rsqrtf(var + 1e-5f));
}

// ---------------------------------------------------------------------------
// RoPE table.
// ---------------------------------------------------------------------------
__global__ __launch_bounds__(256) void rope_table_kernel(
    float2* __restrict__ tab) {
  int idx = blockIdx.x * 256 + threadIdx.x;
  int j = idx & 15;
  int s = idx >> 4;
  float inv_freq = 1.0f / powf(10000.0f, (float)j * 0.0625f);
  float c, sn;
  sincosf((float)s * inv_freq, &c, &sn);
  tab[idx] = make_float2(c, sn);
}

// ---------------------------------------------------------------------------
// 3-term BF16x2 GEMM (R13/R14, proven).
// ---------------------------------------------------------------------------
#define GEMM_SMEM_BYTES (2 * 2 * 128 * 4 * 8 * 2)

#define LN_APPLY()                                                             \
  do {                                                                         \
    if (LNA) {                                                                 \
      const float* gp = lng + k0 + lsl * 8;                                    \
      const float* bp = lnb + k0 + lsl * 8;                                    \
      float4 gg0 = *(const float4*)gp, gg1 = *(const float4*)(gp + 4);         \
      float4 bb0 = *(const float4*)bp, bb1 = *(const float4*)(bp + 4);         \
      va0.x = fmaf((va0.x - mu) * rsd, gg0.x, bb0.x);                          \
      va0.y = fmaf((va0.y - mu) * rsd, gg0.y, bb0.y);                          \
      va0.z = fmaf((va0.z - mu) * rsd, gg0.z, bb0.z);                          \
      va0.w = fmaf((va0.w - mu) * rsd, gg0.w, bb0.w);                          \
      va1.x = fmaf((va1.x - mu) * rsd, gg1.x, bb1.x);                          \
      va1.y = fmaf((va1.y - mu) * rsd, gg1.y, bb1.y);                          \
      va1.z = fmaf((va1.z - mu) * rsd, gg1.z, bb1.z);                          \
      va1.w = fmaf((va1.w - mu) * rsd, gg1.w, bb1.w);                          \
    }                                                                          \
  } while (0)

#define STAGE_STORE(BUF)                                                       \
  do {                                                                         \
    float av[8] = {va0.x, va0.y, va0.z, va0.w, va1.x, va1.y, va1.z, va1.w};    \
    float bv[8] = {vb0.x, vb0.y, vb0.z, vb0.w, vb1.x, vb1.y, vb1.z, vb1.w};    \
    _Pragma("unroll") for (int c = 0; c < 4; c++) {                            \
      uint32_t ah, al, bh, bl;                                                 \
      SPLIT_PAIR(av[2 * c], av[2 * c + 1], ah, al);                            \
      SPLIT_PAIR(bv[2 * c], bv[2 * c + 1], bh, bl);                            \
      As[BUF][lsl][lrow][c] =                                                  \
          make_float2(__uint_as_float(ah), __uint_as_float(al));               \
      Bs[BUF][lsl][lrow][c] =                                                  \
          make_float2(__uint_as_float(bh), __uint_as_float(bl));               \
    }                                                                          \
  } while (0)

#define COMPUTE_STAGE(BUF)                                                     \
  {                                                                            \
    uint32_t bfH[4][2], bfL[4][2];                                             \
    _Pragma("unroll") for (int nt = 0; nt < 4; nt++) {                         \
      const int rw = wn * 32 + nt * 8 + gid;                                   \
      float2 q0 = Bs[BUF][0][rw][tg];                                          \
      float2 q1 = Bs[BUF][1][rw][tg];                                          \
      bfH[nt][0] = __float_as_uint(q0.x); bfH[nt][1] = __float_as_uint(q1.x);  \
      bfL[nt][0] = __float_as_uint(q0.y); bfL[nt][1] = __float_as_uint(q1.y);  \
    }                                                                          \
    _Pragma("unroll") for (int mh = 0; mh < 2; mh++) {                         \
      uint32_t afH[2][4], afL[2][4];                                           \
      _Pragma("unroll") for (int mi = 0; mi < 2; mi++) {                       \
        const int rb = wm * 64 + (mh * 2 + mi) * 16 + gid;                     \
        float2 a00 = As[BUF][0][rb][tg];                                       \
        float2 a01 = As[BUF][0][rb + 8][tg];                                   \
        float2 a10 = As[BUF][1][rb][tg];                                       \
        float2 a11 = As[BUF][1][rb + 8][tg];                                   \
        afH[mi][0] = __float_as_uint(a00.x);                                   \
        afH[mi][1] = __float_as_uint(a01.x);                                   \
        afH[mi][2] = __float_as_uint(a10.x);                                   \
        afH[mi][3] = __float_as_uint(a11.x);                                   \
        afL[mi][0] = __float_as_uint(a00.y);                                   \
        afL[mi][1] = __float_as_uint(a01.y);                                   \
        afL[mi][2] = __float_as_uint(a10.y);                                   \
        afL[mi][3] = __float_as_uint(a11.y);                                   \
      }                                                                        \
      _Pragma("unroll") for (int mi = 0; mi < 2; mi++)                         \
          _Pragma("unroll") for (int nt = 0; nt < 4; nt++)                     \
          mma_bf16(acc[mh * 2 + mi][nt], afH[mi], bfH[nt]);                    \
      _Pragma("unroll") for (int mi = 0; mi < 2; mi++)                         \
          _Pragma("unroll") for (int nt = 0; nt < 4; nt++)                     \
          mma_bf16(acc[mh * 2 + mi][nt], afH[mi], bfL[nt]);                    \
      _Pragma("unroll") for (int mi = 0; mi < 2; mi++)                         \
          _Pragma("unroll") for (int nt = 0; nt < 4; nt++)                     \
          mma_bf16(acc[mh * 2 + mi][nt], afL[mi], bfH[nt]);                    \
    }                                                                          \
  }

template <bool LNA, bool RELU, bool RES, bool ROPE>
__global__ __launch_bounds__(256, 2) void gemm_kernel(
    const float* __restrict__ A, const float* __restrict__ B,
    const float* __restrict__ bias, const float* __restrict__ res,
    const float2* __restrict__ stats, const float* __restrict__ lng,
    const float* __restrict__ lnb, const float2* __restrict__ rope,
    float* __restrict__ C, int M, int N, int K) {
  extern __shared__ float2 smem_dyn[];
  typedef float2 (*SmemT)[2][128][4];
  SmemT As = (SmemT)smem_dyn;
  SmemT Bs = (SmemT)(smem_dyn + 2 * 2 * 128 * 4);

  const int tid = threadIdx.x;
  const int lane = tid & 31;
  const int warp = tid >> 5;
  const int wm = warp >> 2;
  const int wn = warp & 3;
  const int gid = lane >> 2;
  const int tg = lane & 3;

  const int m0 = blockIdx.y * 128;
  const int n0 = blockIdx.x * 128;

  const int lrow = tid >> 1;
  const int lsl = tid & 1;

  const float* Ap = A + (size_t)(m0 + lrow) * K + lsl * 8;
  const float* Bp = B + (size_t)(n0 + lrow) * K + lsl * 8;

  float mu = 0.f, rsd = 1.f;
  if (LNA) {
    float2 st = stats[m0 + lrow];
    mu = st.x;
    rsd = st.y;
  }

  float acc[4][4][4];
#pragma unroll
  for (int i = 0; i < 4; i++)
#pragma unroll
    for (int j = 0; j < 4; j++)
#pragma unroll
      for (int r = 0; r < 4; r++) acc[i][j][r] = 0.f;

  {
    const int k0 = 0;
    float4 va0 = *(const float4*)(Ap);
    float4 va1 = *(const float4*)(Ap + 4);
    float4 vb0 = *(const float4*)(Bp);
    float4 vb1 = *(const float4*)(Bp + 4);
    LN_APPLY();
    STAGE_STORE(0);
    (void)k0;
  }
  __syncthreads();

  int buf = 0;
  for (int k0 = 16; k0 < K; k0 += 16) {
    float4 va0 = *(const float4*)(Ap + k0);
    float4 va1 = *(const float4*)(Ap + k0 + 4);
    float4 vb0 = *(const float4*)(Bp + k0);
    float4 vb1 = *(const float4*)(Bp + k0 + 4);
    LN_APPLY();
    COMPUTE_STAGE(buf);
    const int nxt = buf ^ 1;
    STAGE_STORE(nxt);
    __syncthreads();
    buf = nxt;
  }
  COMPUTE_STAGE(buf);

  const bool doRot = ROPE && (n0 + wn * 32) < 2 * D_MODEL;

#pragma unroll
  for (int mt = 0; mt < 4; mt++) {
    const int row = m0 + wm * 64 + mt * 16 + gid;
    float4 rr[4];
#pragma unroll
    for (int nt = 0; nt < 4; nt++) {
      const int col = n0 + wn * 32 + nt * 8 + tg * 2;
      float2 bb = *(const float2*)&bias[col];
      rr[nt] = make_float4(acc[mt][nt][0] + bb.x, acc[mt][nt][1] + bb.y,
                           acc[mt][nt][2] + bb.x, acc[mt][nt][3] + bb.y);
    }
    if (doRot) {
      const int s = row & (SEQ - 1);
      const int s8 = s + 8;
#pragma unroll
      for (int p = 0; p < 2; p++) {
        const int j0 = p * 8 + tg * 2;
        float2 c0 = rope[s * 16 + j0];
        float2 c1 = rope[s * 16 + j0 + 1];
        float2 d0 = rope[s8 * 16 + j0];
        float2 d1 = rope[s8 * 16 + j0 + 1];
        float4 a = rr[p], q = rr[p + 2];
        rr[p].x = a.x * c0.x - q.x * c0.y;
        rr[p + 2].x = q.x * c0.x + a.x * c0.y;
        rr[p].y = a.y * c1.x - q.y * c1.y;
        rr[p + 2].y = q.y * c1.x + a.y * c1.y;
        rr[p].z = a.z * d0.x - q.z * d0.y;
        rr[p + 2].z = q.z * d0.x + a.z * d0.y;
        rr[p].w = a.w * d1.x - q.w * d1.y;
        rr[p + 2].w = q.w * d1.x + a.w * d1.y;
      }
    }
#pragma unroll
    for (int nt = 0; nt < 4; nt++) {
      const int col = n0 + wn * 32 + nt * 8 + tg * 2;
      float2 r0 = make_float2(rr[nt].x, rr[nt].y);
      float2 r1 = make_float2(rr[nt].z, rr[nt].w);
      if (RELU) {
        r0.x = fmaxf(r0.x, 0.f); r0.y = fmaxf(r0.y, 0.f);
        r1.x = fmaxf(r1.x, 0.f); r1.y = fmaxf(r1.y, 0.f);
      }
      if (RES) {
        float2 q0 = *(const float2*)&res[(size_t)row * N + col];
        float2 q1 = *(const float2*)&res[(size_t)(row + 8) * N + col];
        r0.x += q0.x; r0.y += q0.y;
        r1.x += q1.x; r1.y += q1.y;
      }
      *(float2*)&C[(size_t)row * N + col] = r0;
      *(float2*)&C[(size_t)(row + 8) * N + col] = r1;
    }
  }
}

// ---------------------------------------------------------------------------
// Full LayerNorm (tokenize + final).
// ---------------------------------------------------------------------------
__global__ __launch_bounds__(256) void ln_kernel(
    const float* __restrict__ in, const float* __restrict__ g,
    const float* __restrict__ b, float* __restrict__ out) {
  const int row = blockIdx.x;
  const int t = threadIdx.x;
  float v = in[(size_t)row * D_MODEL + t];

  float s = v;
#pragma unroll
  for (int o = 16; o > 0; o >>= 1) s += __shfl_xor_sync(0xffffffffu, s, o);
  __shared__ float ws[8];
  __shared__ float ws2[8];
  if ((t & 31) == 0) ws[t >> 5] = s;
  __syncthreads();
  float mean = (ws[0] + ws[1] + ws[2] + ws[3] + ws[4] + ws[5] + ws[6] + ws[7]) *
               (1.0f / 256.0f);
  float d = v - mean;
  float s2 = d * d;
#pragma unroll
  for (int o = 16; o > 0; o >>= 1) s2 += __shfl_xor_sync(0xffffffffu, s2, o);
  if ((t & 31) == 0) ws2[t >> 5] = s2;
  __syncthreads();
  float var = (ws2[0] + ws2[1] + ws2[2] + ws2[3] + ws2[4] + ws2[5] + ws2[6] +
               ws2[7]) * (1.0f / 256.0f);
  out[(size_t)row * D_MODEL + t] = d * rsqrtf(var + 1e-5f) * g[t] + b[t];
}

// ---------------------------------------------------------------------------
// Attention: QK^T and AV both on bf16 tensor cores, fp32 softmax.
// Conflict-free strides: PP/VP rows padded to 36 float2 (72 words = 8 mod 32).
// Grid (S/64, B*H), 256 threads (8 warps).
// ---------------------------------------------------------------------------
#define BQ 64
#define BKT 64
#define ATTN_SMEM_BYTES 64000
__global__ __launch_bounds__(256) void attn_kernel(
    const float* __restrict__ qkv, float* __restrict__ out) {
  extern __shared__ char sm[];
  float2(*QP)[18] = (float2(*)[18])sm;                   //  9216 B
  float2(*KP)[18] = (float2(*)[18])(sm + 9216);          //  9216 B
  float2(*VP)[36] = (float2(*)[36])(sm + 18432);         //  9216 B (V^T)
  float(*SP)[68] = (float(*)[68])(sm + 27648);           // 17408 B
  float2(*PP)[36] = (float2(*)[36])(sm + 45056);         // 18432 B
  float* cfs = (float*)(sm + 63488);                     //   256 B
  float* lfin = (float*)(sm + 63744);                    //   256 B

  const int tid = threadIdx.x;
  const int bh = blockIdx.y;
  const int b = bh >> 3;
  const int h = bh & 7;
  const int q0 = blockIdx.x * BQ;
  const float scale = 0.17677669529663687f;

  const int r64 = tid >> 2;
  const int dc = (tid & 3) << 3;
  const int pc = dc >> 1;

  const int lane = tid & 31;
  const int warp = tid >> 5;
  const int gid = lane >> 2;
  const int tg = lane & 3;
  const int m0w = (warp >> 1) * 16;  // QK map
  const int n0w = (warp & 1) * 32;
  const int mg = warp >> 2;          // AV map
  const int ng = warp & 3;

  const int tx = tid & 15;
  const int ty = tid >> 4;

  {
    const float* qb = qkv + (size_t)(b * SEQ + q0 + r64) * 768 + h * 32 + dc;
    float4 q0v = *(const float4*)qb;
    float4 q1v = *(const float4*)(qb + 4);
    float qv[8] = {q0v.x * scale, q0v.y * scale, q0v.z * scale, q0v.w * scale,
                   q1v.x * scale, q1v.y * scale, q1v.z * scale, q1v.w * scale};
#pragma unroll
    for (int c = 0; c < 4; c++) {
      uint32_t hp, lp;
      SPLIT_PAIR(qv[2 * c], qv[2 * c + 1], hp, lp);
      QP[r64][pc + c] = make_float2(__uint_as_float(hp), __uint_as_float(lp));
    }
  }

  float m_i[4], l_i[4];
#pragma unroll
  for (int i = 0; i < 4; i++) { m_i[i] = -INFINITY; l_i[i] = 0.f; }
  float Oa[2][4];
#pragma unroll
  for (int mt = 0; mt < 2; mt++)
#pragma unroll
    for (int r = 0; r < 4; r++) Oa[mt][r] = 0.f;

  for (int kt = 0; kt < SEQ / BKT; kt++) {
    const int k0 = kt * BKT;
    __syncthreads();
    {
      const float* kb =
          qkv + (size_t)(b * SEQ + k0 + r64) * 768 + 256 + h * 32 + dc;
      float4 k0v = *(const float4*)kb;
      float4 k1v = *(const float4*)(kb + 4);
      float kv[8] = {k0v.x, k0v.y, k0v.z, k0v.w, k1v.x, k1v.y, k1v.z, k1v.w};
#pragma unroll
      for (int c = 0; c < 4; c++) {
        uint32_t hp, lp;
        SPLIT_PAIR(kv[2 * c], kv[2 * c + 1], hp, lp);
        KP[r64][pc + c] = make_float2(__uint_as_float(hp), __uint_as_float(lp));
      }
      // V: load [j][d], pair j with j^1 via lane^4 shuffle, store VP[d][j/2].
      const float* vb = kb + 256;
      float4 v0 = *(const float4*)vb;
      float4 v1 = *(const float4*)(vb + 4);
      float vv[8] = {v0.x, v0.y, v0.z, v0.w, v1.x, v1.y, v1.z, v1.w};
      float pv[8];
#pragma unroll
      for (int i = 0; i < 8; i++)
        pv[i] = __shfl_xor_sync(0xffffffffu, vv[i], 4);
      const int jp = r64 >> 1;
      if ((r64 & 1) == 0) {
#pragma unroll
        for (int i = 0; i < 4; i++) {
          uint32_t hp, lp;
          SPLIT_PAIR(vv[i], pv[i], hp, lp);
          VP[dc + i][jp] =
              make_float2(__uint_as_float(hp), __uint_as_float(lp));
        }
      } else {
#pragma unroll
        for (int i = 4; i < 8; i++) {
          uint32_t hp, lp;
          SPLIT_PAIR(pv[i], vv[i], hp, lp);
          VP[dc + i][jp] =
              make_float2(__uint_as_float(hp), __uint_as_float(lp));
        }
      }
    }
    __syncthreads();

    // ---- QK^T via mma (R14, proven) ----
    {
      float acc[4][4];
#pragma unroll
      for (int nt = 0; nt < 4; nt++)
#pragma unroll
        for (int r = 0; r < 4; r++) acc[nt][r] = 0.f;
#pragma unroll
      for (int s = 0; s < 2; s++) {
        uint32_t aH[4], aL[4];
        {
          float2 a00 = QP[m0w + gid][tg + 8 * s];
          float2 a10 = QP[m0w + gid + 8][tg + 8 * s];
          float2 a01 = QP[m0w + gid][tg + 4 + 8 * s];
          float2 a11 = QP[m0w + gid + 8][tg + 4 + 8 * s];
          aH[0] = __float_as_uint(a00.x); aH[1] = __float_as_uint(a10.x);
          aH[2] = __float_as_uint(a01.x); aH[3] = __float_as_uint(a11.x);
          aL[0] = __float_as_uint(a00.y); aL[1] = __float_as_uint(a10.y);
          aL[2] = __float_as_uint(a01.y); aL[3] = __float_as_uint(a11.y);
        }
        uint32_t bH[4][2], bL[4][2];
#pragma unroll
        for (int nt = 0; nt < 4; nt++) {
          float2 k0p = KP[n0w + nt * 8 + gid][tg + 8 * s];
          float2 k1p = KP[n0w + nt * 8 + gid][tg + 4 + 8 * s];
          bH[nt][0] = __float_as_uint(k0p.x);
          bH[nt][1] = __float_as_uint(k1p.x);
          bL[nt][0] = __float_as_uint(k0p.y);
          bL[nt][1] = __float_as_uint(k1p.y);
        }
#pragma unroll
        for (int nt = 0; nt < 4; nt++) mma_bf16(acc[nt], aH, bH[nt]);
#pragma unroll
        for (int nt = 0; nt < 4; nt++) mma_bf16(acc[nt], aH, bL[nt]);
#pragma unroll
        for (int nt = 0; nt < 4; nt++) mma_bf16(acc[nt], aL, bH[nt]);
      }
#pragma unroll
      for (int nt = 0; nt < 4; nt++) {
        const int col = n0w + nt * 8 + 2 * tg;
        *(float2*)&SP[m0w + gid][col] = make_float2(acc[nt][0], acc[nt][1]);
        *(float2*)&SP[m0w + gid + 8][col] = make_float2(acc[nt][2], acc[nt][3]);
      }
    }
    __syncthreads();

    // ---- softmax (fp32) -> packed probs PP + cfs ----
    {
      float s4[4][4];
#pragma unroll
      for (int i = 0; i < 4; i++) {
        float4 v = *(const float4*)&SP[ty * 4 + i][tx * 4];
        s4[i][0] = v.x; s4[i][1] = v.y; s4[i][2] = v.z; s4[i][3] = v.w;
      }
      float cf_i[4];
#pragma unroll
      for (int i = 0; i < 4; i++) {
        float lm = fmaxf(fmaxf(s4[i][0], s4[i][1]), fmaxf(s4[i][2], s4[i][3]));
#pragma unroll
        for (int o = 8; o > 0; o >>= 1)
          lm = fmaxf(lm, __shfl_xor_sync(0xffffffffu, lm, o));
        float mn = fmaxf(m_i[i], lm);
        cf_i[i] = __expf(m_i[i] - mn);
        m_i[i] = mn;
        float p0 = __expf(s4[i][0] - mn);
        float p1 = __expf(s4[i][1] - mn);
        float p2 = __expf(s4[i][2] - mn);
        float p3 = __expf(s4[i][3] - mn);
        uint32_t hp0, lp0, hp1, lp1;
        SPLIT_PAIR(p0, p1, hp0, lp0);
        SPLIT_PAIR(p2, p3, hp1, lp1);
        const int q = ty * 4 + i;
        PP[q][2 * tx] =
            make_float2(__uint_as_float(hp0), __uint_as_float(lp0));
        PP[q][2 * tx + 1] =
            make_float2(__uint_as_float(hp1), __uint_as_float(lp1));
        float ps = p0 + p1 + p2 + p3;
#pragma unroll
        for (int o = 8; o > 0; o >>= 1)
          ps += __shfl_xor_sync(0xffffffffu, ps, o);
        l_i[i] = l_i[i] * cf_i[i] + ps;
      }
      if (tx == 0) {
#pragma unroll
        for (int i = 0; i < 4; i++) cfs[ty * 4 + i] = cf_i[i];
      }
    }
    __syncthreads();

    // ---- AV via mma: O[64][32] += P[64][64] V[64][32] ----
    {
#pragma unroll
      for (int mt = 0; mt < 2; mt++) {
        const int row = mg * 32 + mt * 16 + gid;
        float c0 = cfs[row], c1 = cfs[row + 8];
        Oa[mt][0] *= c0; Oa[mt][1] *= c0;
        Oa[mt][2] *= c1; Oa[mt][3] *= c1;
      }
#pragma unroll
      for (int s = 0; s < 4; s++) {
        uint32_t bH[2], bL[2];
        {
          float2 b0p = VP[ng * 8 + gid][s * 8 + tg];
          float2 b1p = VP[ng * 8 + gid][s * 8 + tg + 4];
          bH[0] = __float_as_uint(b0p.x); bH[1] = __float_as_uint(b1p.x);
          bL[0] = __float_as_uint(b0p.y); bL[1] = __float_as_uint(b1p.y);
        }
        uint32_t aH[2][4], aL[2][4];
#pragma unroll
        for (int mt = 0; mt < 2; mt++) {
          const int row = mg * 32 + mt * 16 + gid;
          float2 p00 = PP[row][s * 8 + tg];
          float2 p10 = PP[row + 8][s * 8 + tg];
          float2 p01 = PP[row][s * 8 + tg + 4];
          float2 p11 = PP[row + 8][s * 8 + tg + 4];
          aH[mt][0] = __float_as_uint(p00.x);
          aH[mt][1] = __float_as_uint(p10.x);
          aH[mt][2] = __float_as_uint(p01.x);
          aH[mt][3] = __float_as_uint(p11.x);
          aL[mt][0] = __float_as_uint(p00.y);
          aL[mt][1] = __float_as_uint(p10.y);
          aL[mt][2] = __float_as_uint(p01.y);
          aL[mt][3] = __float_as_uint(p11.y);
        }
#pragma unroll
        for (int mt = 0; mt < 2; mt++) mma_bf16(Oa[mt], aH[mt], bH);
#pragma unroll
        for (int mt = 0; mt < 2; mt++) mma_bf16(Oa[mt], aH[mt], bL);
#pragma unroll
        for (int mt = 0; mt < 2; mt++) mma_bf16(Oa[mt], aL[mt], bH);
      }
    }
  }

  if (tx == 0) {
#pragma unroll
    for (int i = 0; i < 4; i++) lfin[ty * 4 + i] = l_i[i];
  }
  __syncthreads();

#pragma unroll
  for (int mt = 0; mt < 2; mt++) {
    const int row = mg * 32 + mt * 16 + gid;
    const float inv0 = 1.0f / lfin[row];
    const float inv1 = 1.0f / lfin[row + 8];
    const int col = h * 32 + ng * 8 + 2 * tg;
    *(float2*)&out[(size_t)(b * SEQ + q0 + row) * D_MODEL + col] =
        make_float2(Oa[mt][0] * inv0, Oa[mt][1] * inv0);
    *(float2*)&out[(size_t)(b * SEQ + q0 + row + 8) * D_MODEL + col] =
        make_float2(Oa[mt][2] * inv1, Oa[mt][3] * inv1);
  }
}

// ---------------------------------------------------------------------------
// Launch
// ---------------------------------------------------------------------------
extern "C" void kernel_launch(void* const* d_in, const int* in_sizes, int n_in,
                              void* d_out, int out_size) {
  const float* x         = (const float*)d_in[0];
  const float* tok_w     = (const float*)d_in[1];
  const float* tok_b     = (const float*)d_in[2];
  const float* tnorm_g   = (const float*)d_in[3];
  const float* tnorm_b   = (const float*)d_in[4];
  const float* in_proj_w = (const float*)d_in[5];
  const float* in_proj_b = (const float*)d_in[6];
  const float* out_w     = (const float*)d_in[7];
  const float* out_b     = (const float*)d_in[8];
  const float* ln1_g     = (const float*)d_in[9];
  const float* ln1_b     = (const float*)d_in[10];
  const float* ln2_g     = (const float*)d_in[11];
  const float* ln2_b     = (const float*)d_in[12];
  const float* lin1_w    = (const float*)d_in[13];
  const float* lin1_b    = (const float*)d_in[14];
  const float* lin2_w    = (const float*)d_in[15];
  const float* lin2_b    = (const float*)d_in[16];
  const float* fnorm_g   = (const float*)d_in[17];
  const float* fnorm_b   = (const float*)d_in[18];
  float* out = (float*)d_out;

  float *y, *h, *qkv, *att, *ff;
  float2 *st, *rope;
  cudaGetSymbolAddress((void**)&y, g_y);
  cudaGetSymbolAddress((void**)&h, g_h);
  cudaGetSymbolAddress((void**)&qkv, g_qkv);
  cudaGetSymbolAddress((void**)&att, g_att);
  cudaGetSymbolAddress((void**)&ff, g_ff);
  cudaGetSymbolAddress((void**)&st, g_stats);
  cudaGetSymbolAddress((void**)&rope, g_rope);

  const int M = M_ROWS;
  const int SB = GEMM_SMEM_BYTES;
  cudaFuncSetAttribute(gemm_kernel<false, false, false, false>,
                       cudaFuncAttributeMaxDynamicSharedMemorySize, SB);
  cudaFuncSetAttribute(gemm_kernel<true, false, false, true>,
                       cudaFuncAttributeMaxDynamicSharedMemorySize, SB);
  cudaFuncSetAttribute(gemm_kernel<false, false, true, false>,
                       cudaFuncAttributeMaxDynamicSharedMemorySize, SB);
  cudaFuncSetAttribute(gemm_kernel<true, true, false, false>,
                       cudaFuncAttributeMaxDynamicSharedMemorySize, SB);
  cudaFuncSetAttribute(attn_kernel,
                       cudaFuncAttributeMaxDynamicSharedMemorySize,
                       ATTN_SMEM_BYTES);

  dim3 blk(256);

  rope_table_kernel<<<SEQ * 16 / 256, blk>>>(rope);

  gemm_kernel<false, false, false, false><<<dim3(2, M / 128), blk, SB>>>(
      x, tok_w, tok_b, nullptr, nullptr, nullptr, nullptr, nullptr, y, M,
      D_MODEL, T_IN);
  ln_kernel<<<M, blk>>>(y, tnorm_g, tnorm_b, h);

  for (int i = 0; i < N_LAYERS; i++) {
    ln_stats_kernel<<<M / 8, blk>>>(h, st);
    gemm_kernel<true, false, false, true><<<dim3(6, M / 128), blk, SB>>>(
        h, in_proj_w + (size_t)i * 768 * D_MODEL, in_proj_b + i * 768, nullptr,
        st, ln1_g + i * D_MODEL, ln1_b + i * D_MODEL, rope, qkv, M, 768,
        D_MODEL);
    attn_kernel<<<dim3(SEQ / BQ, 16 * N_HEADS), blk, ATTN_SMEM_BYTES>>>(qkv,
                                                                        att);
    gemm_kernel<false, false, true, false><<<dim3(2, M / 128), blk, SB>>>(
        att, out_w + (size_t)i * D_MODEL * D_MODEL, out_b + i * D_MODEL, h,
        nullptr, nullptr, nullptr, nullptr, h, M, D_MODEL, D_MODEL);
    ln_stats_kernel<<<M / 8, blk>>>(h, st);
    gemm_kernel<true, true, false, false><<<dim3(8, M / 128), blk, SB>>>(
        h, lin1_w + (size_t)i * FF_DIM * D_MODEL, lin1_b + i * FF_DIM, nullptr,
        st, ln2_g + i * D_MODEL, ln2_b + i * D_MODEL, nullptr, ff, M, FF_DIM,
        D_MODEL);
    gemm_kernel<false, false, true, false><<<dim3(2, M / 128), blk, SB>>>(
        ff, lin2_w + (size_t)i * D_MODEL * FF_DIM, lin2_b + i * D_MODEL, h,
        nullptr, nullptr, nullptr, nullptr, h, M, D_MODEL, FF_DIM);
  }

  ln_kernel<<<M, blk>>>(h, fnorm_g, fnorm_b, out);
}